// round 12
// baseline (speedup 1.0000x reference)
#include <cuda_runtime.h>
#include <cstdint>

// ---------------- problem dims ----------------
#define NB 64
#define L1_IN 16000
#define C1 128
#define K1 84
#define L1 3980
#define P1 1990
#define L2 1991
#define P2 995
#define L3 994
#define P3 497
#define L5 499
#define P5 249
#define NCLS 35

// Packed-bit permutation (activations AND weights):
//   word w, bit b  <->  channel c = 128*(w>>2) + 4*b + (w&3)
// GEMM k-byte j = w*32 + b maps to channel perm(j) = 128*((j>>5)>>2) + 4*(j&31) + ((j>>5)&3)

// ---------------- device scratch ----------------
__device__ float    g_w1t[K1 * C1];                     // [k][c], +-0.1
__device__ __align__(16) int8_t g_wi2[2 * 4 * 64 * 144];   // int8 weight images [ct][tap][co][CINP]
__device__ __align__(16) int8_t g_wi3[4 * 4 * 64 * 144];
__device__ __align__(16) int8_t g_wi5[8 * 3 * 64 * 272];
__device__ uint32_t g_wfcp[NCLS * P5 * 16];             // [m][t][word]

__device__ float    g_h1[(size_t)NB * L1 * C1];
__device__ short    g_h2s[(size_t)NB * L2 * 128];
__device__ short    g_h3s[(size_t)NB * L3 * 256];
__device__ short    g_h5s[(size_t)NB * L5 * 512];
__device__ uint32_t g_a1[(size_t)NB * P1 * 4];          // packed bits [n][t][word]
__device__ uint32_t g_a2[(size_t)NB * P2 * 4];
__device__ uint32_t g_a3[(size_t)NB * P3 * 8];
__device__ uint32_t g_a5[(size_t)NB * P5 * 16];

__device__ float2   g_fpart[128 * 8000];                // conv1 stat partials
__device__ int2     g_ipart[262144];                    // binary conv stat partials
__device__ float    g_A[512], g_B[512];                 // binarize coeffs per channel

// ---------------- helpers ----------------
__device__ __forceinline__ unsigned long long ffma2_(unsigned long long a,
                                                     unsigned long long b,
                                                     unsigned long long c) {
    unsigned long long d;
    asm("fma.rn.f32x2 %0, %1, %2, %3;" : "=l"(d) : "l"(a), "l"(b), "l"(c));
    return d;
}
__device__ __forceinline__ unsigned long long dup2(float v) {
    unsigned long long r;
    asm("mov.b64 %0, {%1, %1};" : "=l"(r) : "f"(v));
    return r;
}
__device__ __forceinline__ unsigned long long pack2(float lo, float hi) {
    unsigned long long r;
    asm("mov.b64 %0, {%1, %2};" : "=l"(r) : "f"(lo), "f"(hi));
    return r;
}
__device__ __forceinline__ void unpack2(unsigned long long v, float& lo, float& hi) {
    asm("mov.b64 {%0, %1}, %2;" : "=f"(lo), "=f"(hi) : "l"(v));
}
__device__ __forceinline__ void imma16832(int& c0, int& c1, int& c2, int& c3,
                                          uint32_t a0, uint32_t a1, uint32_t a2, uint32_t a3,
                                          uint32_t b0, uint32_t b1) {
    asm volatile(
        "mma.sync.aligned.m16n8k32.row.col.s32.s8.s8.s32 "
        "{%0,%1,%2,%3}, {%4,%5,%6,%7}, {%8,%9}, {%0,%1,%2,%3};"
        : "+r"(c0), "+r"(c1), "+r"(c2), "+r"(c3)
        : "r"(a0), "r"(a1), "r"(a2), "r"(a3), "r"(b0), "r"(b1));
}

// ---------------- fused weight prep ----------------
#define PS_W1  10752
#define PSI2   (2 * 4 * 64 * 144)
#define PSI3   (4 * 4 * 64 * 144)
#define PSI5   (8 * 3 * 64 * 272)
#define PS_WFC 139440
#define PTOT (PS_W1 + PSI2 + PSI3 + PSI5 + PS_WFC)

// one int8 byte of a weight image; layout [ct][tap][co64][CINP]
__device__ __forceinline__ void prep_wimg(const float* __restrict__ w, int8_t* img,
                                          int Cin, int K, int i) {
    const int CINP = Cin + 16;
    int j = i % CINP;
    int rest = i / CINP;
    int co_l = rest % 64;
    rest /= 64;
    int tap = rest % K;
    int ct = rest / K;
    int gco = ct * 64 + co_l;
    int8_t v = 0;
    if (j < Cin) {
        int wd = j >> 5, b = j & 31;
        int c = 128 * (wd >> 2) + 4 * b + (wd & 3);
        v = (w[((size_t)gco * Cin + c) * K + tap] >= 0.f) ? (int8_t)1 : (int8_t)-1;
    }
    img[(size_t)i] = v;   // i already linearizes [ct][tap][co][CINP]
}

__global__ void k_prep_all(const float* __restrict__ w1, const float* __restrict__ w2,
                           const float* __restrict__ w3, const float* __restrict__ w5,
                           const float* __restrict__ wfc) {
    int gid = blockIdx.x * blockDim.x + threadIdx.x;
    if (gid < PS_W1) {
        int co = gid / K1, k = gid % K1;
        g_w1t[k * C1 + co] = (w1[gid] >= 0.f) ? 0.1f : -0.1f;
        return;
    }
    gid -= PS_W1;
    if (gid < PSI2) { prep_wimg(w2, g_wi2, 128, 4, gid); return; }
    gid -= PSI2;
    if (gid < PSI3) { prep_wimg(w3, g_wi3, 128, 4, gid); return; }
    gid -= PSI3;
    if (gid < PSI5) { prep_wimg(w5, g_wi5, 256, 3, gid); return; }
    gid -= PSI5;
    if (gid < PS_WFC) {
        int i = gid;
        int word = i % 16;
        int rest = i / 16;
        int t = rest % P5;
        int m = rest / P5;
        uint32_t bits = 0;
        for (int b = 0; b < 32; b++) {
            int c = 128 * (word >> 2) + 4 * b + (word & 3);
            if (wfc[(size_t)m * (512 * P5) + (size_t)c * P5 + t] >= 0.f) bits |= (1u << b);
        }
        g_wfcp[((size_t)m * P5 + t) * 16 + word] = bits;
        return;
    }
}

// ---------------- conv1: fp32, stride 4, K=84, fused stats ----------------
// Tile 64t x 128c per block; thread = 8c x 4t (dup-reuse 4x, weights via LDS.128).
// Per-output k-summation order identical to previous rounds -> bit-identical h1.
#define C1_GX 63            // ceil(3980/64)
__global__ __launch_bounds__(256) void k_conv1(const float* __restrict__ x,
                                               const float* __restrict__ b1) {
    __shared__ __align__(16) float ws2[K1 * C1];    // [k][c]; reused as sred later
    __shared__ __align__(16) float xs[340];         // 64*4 + 84 - 4 = 336 used
    int n = blockIdx.y;
    int tb = blockIdx.x * 64;
    int tid = threadIdx.x;

    for (int i = tid; i < K1 * C1; i += 256) ws2[i] = g_w1t[i];
    for (int i = tid; i < 336; i += 256) {
        int xi = tb * 4 + i;
        xs[i] = (xi < L1_IN) ? x[(size_t)n * L1_IN + xi] : 0.f;
    }
    __syncthreads();

    int cg = tid & 15, tg = tid >> 4;
    int c0 = cg * 8, t0 = tg * 4;
    const float4* xf4 = reinterpret_cast<const float4*>(xs);

    unsigned long long acc2[4][4] = {};             // [cpair][t]
#pragma unroll
    for (int k4 = 0; k4 < 21; k4++) {
        float4 xv[4];
#pragma unroll
        for (int i = 0; i < 4; i++) xv[i] = xf4[t0 + i + k4];
#pragma unroll
        for (int j = 0; j < 4; j++) {
            int k = k4 * 4 + j;
            float4 wa = *reinterpret_cast<const float4*>(&ws2[k * C1 + c0]);
            float4 wb = *reinterpret_cast<const float4*>(&ws2[k * C1 + c0 + 4]);
            unsigned long long w0 = pack2(wa.x, wa.y);
            unsigned long long w1 = pack2(wa.z, wa.w);
            unsigned long long w2 = pack2(wb.x, wb.y);
            unsigned long long w3 = pack2(wb.z, wb.w);
#pragma unroll
            for (int i = 0; i < 4; i++) {
                unsigned long long xd = dup2(reinterpret_cast<const float*>(xv)[i * 4 + j]);
                acc2[0][i] = ffma2_(w0, xd, acc2[0][i]);
                acc2[1][i] = ffma2_(w1, xd, acc2[1][i]);
                acc2[2][i] = ffma2_(w2, xd, acc2[2][i]);
                acc2[3][i] = ffma2_(w3, xd, acc2[3][i]);
            }
        }
    }

    float4 bb0 = *reinterpret_cast<const float4*>(&b1[c0]);
    float4 bb1 = *reinterpret_cast<const float4*>(&b1[c0 + 4]);
    float bv[8] = {bb0.x, bb0.y, bb0.z, bb0.w, bb1.x, bb1.y, bb1.z, bb1.w};
    float ssum[8] = {}, ssq[8] = {};
#pragma unroll
    for (int i = 0; i < 4; i++) {
        int t = tb + t0 + i;
        if (t < L1) {
            float o[8];
#pragma unroll
            for (int cp = 0; cp < 4; cp++) {
                float lo, hi;
                unpack2(acc2[cp][i], lo, hi);
                o[2 * cp] = lo + bv[2 * cp];
                o[2 * cp + 1] = hi + bv[2 * cp + 1];
            }
            float* hp = &g_h1[((size_t)n * L1 + t) * C1 + c0];
            *reinterpret_cast<float4*>(hp) = make_float4(o[0], o[1], o[2], o[3]);
            *reinterpret_cast<float4*>(hp + 4) = make_float4(o[4], o[5], o[6], o[7]);
#pragma unroll
            for (int j = 0; j < 8; j++) { ssum[j] += o[j]; ssq[j] += o[j] * o[j]; }
        }
    }
    __syncthreads();
    float2* sred = reinterpret_cast<float2*>(ws2);   // 16*128*8 = 16KB << 43KB, weights dead
#pragma unroll
    for (int j = 0; j < 8; j++) sred[tg * 128 + c0 + j] = make_float2(ssum[j], ssq[j]);
    __syncthreads();
    if (tid < 128) {
        float s = 0.f, q = 0.f;
#pragma unroll
        for (int g = 0; g < 16; g++) { float2 vv = sred[g * 128 + tid]; s += vv.x; q += vv.y; }
        int part = blockIdx.x * NB + n;
        g_fpart[(size_t)tid * (C1_GX * NB) + part] = make_float2(s, q);
    }
}

// ---------------- stat finalize ----------------
__global__ void k_stat2f(const float* __restrict__ gamma, const float* __restrict__ beta,
                         int NPART, double Rinv) {
    __shared__ double ss[256], sq[256];
    int c = blockIdx.x, tid = threadIdx.x;
    double s = 0.0, q = 0.0;
    for (int i = tid; i < NPART; i += 256) {
        float2 vv = g_fpart[(size_t)c * NPART + i];
        s += vv.x; q += vv.y;
    }
    ss[tid] = s; sq[tid] = q;
    __syncthreads();
    for (int o = 128; o > 0; o >>= 1) {
        if (tid < o) { ss[tid] += ss[tid + o]; sq[tid] += sq[tid + o]; }
        __syncthreads();
    }
    if (tid == 0) {
        double mu = ss[0] * Rinv;
        double var = sq[0] * Rinv - mu * mu;
        double inv = rsqrt(var + 1e-5);
        double A = inv * (double)gamma[c];
        g_A[c] = (float)A;
        g_B[c] = (float)((double)beta[c] - mu * A);
    }
}

__global__ void k_stat2i(const float* __restrict__ bias, const float* __restrict__ gamma,
                         const float* __restrict__ beta, int NPART, double Rinv) {
    __shared__ long long ss[256], sq[256];
    int c = blockIdx.x, tid = threadIdx.x;
    long long s = 0, q = 0;
    for (int i = tid; i < NPART; i += 256) {
        int2 vv = g_ipart[(size_t)c * NPART + i];
        s += vv.x; q += vv.y;
    }
    ss[tid] = s; sq[tid] = q;
    __syncthreads();
    for (int o = 128; o > 0; o >>= 1) {
        if (tid < o) { ss[tid] += ss[tid + o]; sq[tid] += sq[tid + o]; }
        __syncthreads();
    }
    if (tid == 0) {
        double mu_s = (double)ss[0] * Rinv;
        double Es2 = (double)sq[0] * Rinv;
        double var_h = 0.01 * (Es2 - mu_s * mu_s);
        double b = bias[c];
        double mu_h = 0.1 * mu_s + b;
        double inv = rsqrt(var_h + 1e-5);
        double g = gamma[c];
        double A = 0.1 * inv * g;
        double B = (b - mu_h) * inv * g + (double)beta[c];
        g_A[c] = (float)A;
        g_B[c] = (float)B;
    }
}

// ---------------- binarize + pool(2), vectorized nibble-ballot ----------------
__global__ void k_binpool_f2(const float* __restrict__ h, uint32_t* __restrict__ a) {
    int gw = blockIdx.x * 8 + (threadIdx.x >> 5);
    if (gw >= NB * P1) return;
    int lane = threadIdx.x & 31;
    int to = gw % P1, n = gw / P1;
    size_t base = ((size_t)n * L1 + (size_t)2 * to) * 128 + lane * 4;
    float4 v0 = *reinterpret_cast<const float4*>(h + base);
    float4 v1 = *reinterpret_cast<const float4*>(h + base + 128);
    float4 A = *reinterpret_cast<const float4*>(g_A + lane * 4);
    float4 B = *reinterpret_cast<const float4*>(g_B + lane * 4);
    unsigned m0 = __ballot_sync(0xFFFFFFFFu,
        (fmaf(v0.x, A.x, B.x) >= 0.f) | (fmaf(v1.x, A.x, B.x) >= 0.f));
    unsigned m1 = __ballot_sync(0xFFFFFFFFu,
        (fmaf(v0.y, A.y, B.y) >= 0.f) | (fmaf(v1.y, A.y, B.y) >= 0.f));
    unsigned m2 = __ballot_sync(0xFFFFFFFFu,
        (fmaf(v0.z, A.z, B.z) >= 0.f) | (fmaf(v1.z, A.z, B.z) >= 0.f));
    unsigned m3 = __ballot_sync(0xFFFFFFFFu,
        (fmaf(v0.w, A.w, B.w) >= 0.f) | (fmaf(v1.w, A.w, B.w) >= 0.f));
    if (lane == 0)
        *reinterpret_cast<uint4*>(a + (size_t)gw * 4) = make_uint4(m0, m1, m2, m3);
}

template <int C, int L, int LO>
__global__ void k_binpool_i2(const short* __restrict__ h, uint32_t* __restrict__ a) {
    constexpr int HW = C / 128;
    int gw = blockIdx.x * 8 + (threadIdx.x >> 5);
    if (gw >= NB * LO * HW) return;
    int lane = threadIdx.x & 31;
    int hwi = gw % HW;
    int r = gw / HW;
    int to = r % LO, n = r / LO;
    int c0 = hwi * 128 + lane * 4;
    size_t base = ((size_t)n * L + (size_t)2 * to) * C + c0;
    short4 s0 = *reinterpret_cast<const short4*>(h + base);
    short4 s1 = *reinterpret_cast<const short4*>(h + base + C);
    float4 A = *reinterpret_cast<const float4*>(g_A + c0);
    float4 B = *reinterpret_cast<const float4*>(g_B + c0);
    unsigned m0 = __ballot_sync(0xFFFFFFFFu,
        (fmaf((float)s0.x, A.x, B.x) >= 0.f) | (fmaf((float)s1.x, A.x, B.x) >= 0.f));
    unsigned m1 = __ballot_sync(0xFFFFFFFFu,
        (fmaf((float)s0.y, A.y, B.y) >= 0.f) | (fmaf((float)s1.y, A.y, B.y) >= 0.f));
    unsigned m2 = __ballot_sync(0xFFFFFFFFu,
        (fmaf((float)s0.z, A.z, B.z) >= 0.f) | (fmaf((float)s1.z, A.z, B.z) >= 0.f));
    unsigned m3 = __ballot_sync(0xFFFFFFFFu,
        (fmaf((float)s0.w, A.w, B.w) >= 0.f) | (fmaf((float)s1.w, A.w, B.w) >= 0.f));
    if (lane == 0)
        *reinterpret_cast<uint4*>(a + (size_t)r * (C / 32) + hwi * 4) =
            make_uint4(m0, m1, m2, m3);
}

// ---------------- binary conv via int8 mma.sync (IMMA), fused int stats ----------------
// Tile: 128 t x 64 co per block. A = activations int8 (expanded from bits, pad rows = 0),
// B = weight int8 images (global, pre-expanded). CINP = CIN+16 row padding -> conflict-free frags.
template <int CIN, int COUT, int K, int PAD>
__global__ __launch_bounds__(256, 1) void k_convi(const uint32_t* __restrict__ a,
                                                  const int8_t* __restrict__ wimg,
                                                  short* __restrict__ h,
                                                  int Lin, int Lout, int NPART) {
    constexpr int W = CIN / 32;
    constexpr int CINP = CIN + 16;
    constexpr int ROWS = 128 + K - 1;
    constexpr int CH = CIN / 32;
    constexpr int WB = K * 64 * CINP;
    extern __shared__ __align__(16) char dsm[];
    int8_t* Ws = reinterpret_cast<int8_t*>(dsm);
    int8_t* As = reinterpret_cast<int8_t*>(dsm + WB);
    __shared__ int2 sred[16 * 64];

    int tid = threadIdx.x;
    int n = blockIdx.z;
    int cob = blockIdx.y * 64;
    int tb = blockIdx.x * 128;

    // load weight image (plain copy)
    {
        const uint4* src = reinterpret_cast<const uint4*>(wimg + (size_t)blockIdx.y * WB);
        uint4* dst = reinterpret_cast<uint4*>(Ws);
        for (int i = tid; i < WB / 16; i += 256) dst[i] = src[i];
    }
    // expand activations bits -> +-1 int8 (pad rows -> 0); bit=1 -> +1 (0x01), bit=0 -> -1 (0xFF)
    for (int idx = tid; idx < ROWS * W; idx += 256) {
        int r = idx / W;
        int w = idx % W;
        int t = tb + r - PAD;
        bool valid = (t >= 0 && t < Lin);
        uint32_t bits = valid ? a[((size_t)n * Lin + t) * W + w] : 0u;
        uint32_t* dst = reinterpret_cast<uint32_t*>(As + r * CINP + w * 32);
#pragma unroll
        for (int p = 0; p < 8; p++) {
            uint32_t nib = (bits >> (4 * p)) & 15u;
            uint32_t mask = (nib * 0x00204081u) & 0x01010101u;
            dst[p] = valid ? (0xFFFFFFFFu ^ (mask * 0xFEu)) : 0u;
        }
    }
    __syncthreads();

    int wid = tid >> 5, lane = tid & 31;
    int g = lane >> 2, tig = lane & 3;
    int wc = wid >> 2, wt = wid & 3;           // 2 co-halves x 4 t-quarters

    int cfr[2][4][4] = {};                     // [mt][nt][reg]
#pragma unroll
    for (int k = 0; k < K; k++) {
#pragma unroll
        for (int ch = 0; ch < CH; ch++) {
            int kb = ch * 32 + tig * 4;
            uint32_t afr[2][4];
#pragma unroll
            for (int mt = 0; mt < 2; mt++) {
                const int8_t* ap = As + (wt * 32 + mt * 16 + k + g) * CINP + kb;
                afr[mt][0] = *reinterpret_cast<const uint32_t*>(ap);
                afr[mt][1] = *reinterpret_cast<const uint32_t*>(ap + 8 * CINP);
                afr[mt][2] = *reinterpret_cast<const uint32_t*>(ap + 16);
                afr[mt][3] = *reinterpret_cast<const uint32_t*>(ap + 8 * CINP + 16);
            }
#pragma unroll
            for (int nt = 0; nt < 4; nt++) {
                const int8_t* bp = Ws + (k * 64 + wc * 32 + nt * 8 + g) * CINP + kb;
                uint32_t b0 = *reinterpret_cast<const uint32_t*>(bp);
                uint32_t b1 = *reinterpret_cast<const uint32_t*>(bp + 16);
                imma16832(cfr[0][nt][0], cfr[0][nt][1], cfr[0][nt][2], cfr[0][nt][3],
                          afr[0][0], afr[0][1], afr[0][2], afr[0][3], b0, b1);
                imma16832(cfr[1][nt][0], cfr[1][nt][1], cfr[1][nt][2], cfr[1][nt][3],
                          afr[1][0], afr[1][1], afr[1][2], afr[1][3], b0, b1);
            }
        }
    }
    __syncthreads();                           // A region dead -> reuse as staging
    short* stage = reinterpret_cast<short*>(As);
#pragma unroll
    for (int mt = 0; mt < 2; mt++) {
#pragma unroll
        for (int nt = 0; nt < 4; nt++) {
            int tl = wt * 32 + mt * 16 + g;
            int cl = wc * 32 + nt * 8 + tig * 2;
            stage[tl * 64 + cl]           = (short)cfr[mt][nt][0];
            stage[tl * 64 + cl + 1]       = (short)cfr[mt][nt][1];
            stage[(tl + 8) * 64 + cl]     = (short)cfr[mt][nt][2];
            stage[(tl + 8) * 64 + cl + 1] = (short)cfr[mt][nt][3];
        }
    }
    __syncthreads();

    // epilogue: coalesced short4 stores + exact int stats
    int co0 = (tid & 15) * 4;
    int t0 = (tid >> 4) * 8;
    int ssum[4] = {}, ssq[4] = {};
#pragma unroll
    for (int i = 0; i < 8; i++) {
        int t = tb + t0 + i;
        short4 v = *reinterpret_cast<const short4*>(&stage[(t0 + i) * 64 + co0]);
        if (t < Lout) {
            *reinterpret_cast<short4*>(&h[((size_t)n * Lout + t) * COUT + cob + co0]) = v;
            ssum[0] += v.x; ssq[0] += (int)v.x * v.x;
            ssum[1] += v.y; ssq[1] += (int)v.y * v.y;
            ssum[2] += v.z; ssq[2] += (int)v.z * v.z;
            ssum[3] += v.w; ssq[3] += (int)v.w * v.w;
        }
    }
    int grp = tid >> 4;
#pragma unroll
    for (int j = 0; j < 4; j++) sred[grp * 64 + co0 + j] = make_int2(ssum[j], ssq[j]);
    __syncthreads();
    if (tid < 64) {
        int s = 0, q = 0;
#pragma unroll
        for (int gg = 0; gg < 16; gg++) { int2 vv = sred[gg * 64 + tid]; s += vv.x; q += vv.y; }
        int part = blockIdx.x * NB + n;
        g_ipart[(size_t)(cob + tid) * NPART + part] = make_int2(s, q);
    }
}

// ---------------- FC via popcount, a5 staged in smem ----------------
__global__ __launch_bounds__(256) void k_fc(float* __restrict__ out) {
    __shared__ uint32_t a5s[P5 * 16];
    int n = blockIdx.x;
    int tid = threadIdx.x;
    int wid = tid >> 5, lane = tid & 31;
    const uint32_t* av = &g_a5[(size_t)n * P5 * 16];
    for (int i = tid; i < P5 * 16; i += 256) a5s[i] = av[i];
    __syncthreads();
    for (int m = wid; m < NCLS; m += 8) {
        const uint32_t* wv = &g_wfcp[(size_t)m * P5 * 16];
        int p = 0;
        for (int i = lane; i < P5 * 16; i += 32) p += __popc(a5s[i] ^ wv[i]);
#pragma unroll
        for (int o = 16; o > 0; o >>= 1) p += __shfl_xor_sync(0xFFFFFFFFu, p, o);
        if (lane == 0) out[n * NCLS + m] = 0.1f * (float)(P5 * 512 - 2 * p);
    }
}

// ---------------- launch ----------------
extern "C" void kernel_launch(void* const* d_in, const int* in_sizes, int n_in,
                              void* d_out, int out_size) {
    const float* x   = (const float*)d_in[0];
    const float* w1  = (const float*)d_in[1];
    const float* b1  = (const float*)d_in[2];
    const float* g1  = (const float*)d_in[3];
    const float* be1 = (const float*)d_in[4];
    const float* w2  = (const float*)d_in[5];
    const float* b2  = (const float*)d_in[6];
    const float* g2  = (const float*)d_in[7];
    const float* be2 = (const float*)d_in[8];
    const float* w3  = (const float*)d_in[9];
    const float* b3  = (const float*)d_in[10];
    const float* g3  = (const float*)d_in[11];
    const float* be3 = (const float*)d_in[12];
    const float* w5  = (const float*)d_in[13];
    const float* b5  = (const float*)d_in[14];
    const float* g5  = (const float*)d_in[15];
    const float* be5 = (const float*)d_in[16];
    const float* wfc = (const float*)d_in[17];

    void *p_wi2, *p_wi3, *p_wi5;
    void *p_a1, *p_a2, *p_a3, *p_a5, *p_h2, *p_h3, *p_h5, *p_h1;
    cudaGetSymbolAddress(&p_wi2, g_wi2);
    cudaGetSymbolAddress(&p_wi3, g_wi3);
    cudaGetSymbolAddress(&p_wi5, g_wi5);
    cudaGetSymbolAddress(&p_a1, g_a1);
    cudaGetSymbolAddress(&p_a2, g_a2);
    cudaGetSymbolAddress(&p_a3, g_a3);
    cudaGetSymbolAddress(&p_a5, g_a5);
    cudaGetSymbolAddress(&p_h1, g_h1);
    cudaGetSymbolAddress(&p_h2, g_h2s);
    cudaGetSymbolAddress(&p_h3, g_h3s);
    cudaGetSymbolAddress(&p_h5, g_h5s);

    const int SM23 = 4 * 64 * 144 + 131 * 144;      // 55728
    const int SM5  = 3 * 64 * 272 + 130 * 272;      // 87584
    cudaFuncSetAttribute(k_convi<128, 128, 4, 2>, cudaFuncAttributeMaxDynamicSharedMemorySize, SM23);
    cudaFuncSetAttribute(k_convi<128, 256, 4, 1>, cudaFuncAttributeMaxDynamicSharedMemorySize, SM23);
    cudaFuncSetAttribute(k_convi<256, 512, 3, 2>, cudaFuncAttributeMaxDynamicSharedMemorySize, SM5);

    // fused weight prep
    k_prep_all<<<(PTOT + 255) / 256, 256>>>(w1, w2, w3, w5, wfc);

    // layer 1
    k_conv1<<<dim3(C1_GX, NB), 256>>>(x, b1);
    k_stat2f<<<C1, 256>>>(g1, be1, C1_GX * NB, 1.0 / (double)(NB * L1));
    {
        int nw = NB * P1;
        k_binpool_f2<<<(nw + 7) / 8, 256>>>((const float*)p_h1, (uint32_t*)p_a1);
    }
    // layer 2 (IMMA)
    k_convi<128, 128, 4, 2><<<dim3(16, 2, NB), 256, SM23>>>(
        (const uint32_t*)p_a1, (const int8_t*)p_wi2, (short*)p_h2, P1, L2, 16 * NB);
    k_stat2i<<<128, 256>>>(b2, g2, be2, 16 * NB, 1.0 / (double)(NB * L2));
    {
        int nw = NB * P2;
        k_binpool_i2<128, L2, P2><<<(nw + 7) / 8, 256>>>((const short*)p_h2, (uint32_t*)p_a2);
    }
    // layer 3 (IMMA)
    k_convi<128, 256, 4, 1><<<dim3(8, 4, NB), 256, SM23>>>(
        (const uint32_t*)p_a2, (const int8_t*)p_wi3, (short*)p_h3, P2, L3, 8 * NB);
    k_stat2i<<<256, 256>>>(b3, g3, be3, 8 * NB, 1.0 / (double)(NB * L3));
    {
        int nw = NB * P3 * 2;
        k_binpool_i2<256, L3, P3><<<(nw + 7) / 8, 256>>>((const short*)p_h3, (uint32_t*)p_a3);
    }
    // layer 5 (IMMA)
    k_convi<256, 512, 3, 2><<<dim3(4, 8, NB), 256, SM5>>>(
        (const uint32_t*)p_a3, (const int8_t*)p_wi5, (short*)p_h5, P3, L5, 4 * NB);
    k_stat2i<<<512, 256>>>(b5, g5, be5, 4 * NB, 1.0 / (double)(NB * L5));
    {
        int nw = NB * P5 * 4;
        k_binpool_i2<512, L5, P5><<<(nw + 7) / 8, 256>>>((const short*)p_h5, (uint32_t*)p_a5);
    }
    // fc
    k_fc<<<NB, 256>>>((float*)d_out);
}

// round 13
// speedup vs baseline: 1.1907x; 1.1907x over previous
#include <cuda_runtime.h>
#include <cstdint>

// ---------------- problem dims ----------------
#define NB 64
#define L1_IN 16000
#define C1 128
#define K1 84
#define L1 3980
#define P1 1990
#define L2 1991
#define P2 995
#define L3 994
#define P3 497
#define L5 499
#define P5 249
#define NCLS 35

// Packed-bit permutation (activations AND weights):
//   word w, bit b  <->  channel c = 128*(w>>2) + 4*b + (w&3)
// GEMM k-byte j = w*32 + b maps to channel perm(j) = 128*((j>>5)>>2) + 4*(j&31) + ((j>>5)&3)

// ---------------- device scratch ----------------
__device__ float    g_w1t[K1 * C1];                     // [k][c], +-0.1
__device__ __align__(16) int8_t g_wi2[2 * 4 * 64 * 144];   // int8 weight images [ct][tap][co][CINP]
__device__ __align__(16) int8_t g_wi3[4 * 4 * 64 * 144];
__device__ __align__(16) int8_t g_wi5[8 * 3 * 64 * 272];
__device__ uint32_t g_wfcp[NCLS * P5 * 16];             // [m][t][word]

__device__ float    g_h1[(size_t)NB * L1 * C1];
__device__ short    g_h2s[(size_t)NB * L2 * 128];
__device__ short    g_h3s[(size_t)NB * L3 * 256];
__device__ short    g_h5s[(size_t)NB * L5 * 512];
__device__ uint32_t g_a1[(size_t)NB * P1 * 4];          // packed bits [n][t][word]
__device__ uint32_t g_a2[(size_t)NB * P2 * 4];
__device__ uint32_t g_a3[(size_t)NB * P3 * 8];
__device__ uint32_t g_a5[(size_t)NB * P5 * 16];

__device__ float2   g_fpart[128 * 8000];                // conv1 stat partials
__device__ int2     g_ipart[262144];                    // binary conv stat partials
__device__ float    g_A[512], g_B[512];                 // binarize coeffs per channel

// ---------------- helpers ----------------
__device__ __forceinline__ unsigned long long ffma2_(unsigned long long a,
                                                     unsigned long long b,
                                                     unsigned long long c) {
    unsigned long long d;
    asm("fma.rn.f32x2 %0, %1, %2, %3;" : "=l"(d) : "l"(a), "l"(b), "l"(c));
    return d;
}
__device__ __forceinline__ unsigned long long dup2(float v) {
    unsigned long long r;
    asm("mov.b64 %0, {%1, %1};" : "=l"(r) : "f"(v));
    return r;
}
__device__ __forceinline__ void unpack2(unsigned long long v, float& lo, float& hi) {
    asm("mov.b64 {%0, %1}, %2;" : "=f"(lo), "=f"(hi) : "l"(v));
}
__device__ __forceinline__ void imma16832(int& c0, int& c1, int& c2, int& c3,
                                          uint32_t a0, uint32_t a1, uint32_t a2, uint32_t a3,
                                          uint32_t b0, uint32_t b1) {
    asm volatile(
        "mma.sync.aligned.m16n8k32.row.col.s32.s8.s8.s32 "
        "{%0,%1,%2,%3}, {%4,%5,%6,%7}, {%8,%9}, {%0,%1,%2,%3};"
        : "+r"(c0), "+r"(c1), "+r"(c2), "+r"(c3)
        : "r"(a0), "r"(a1), "r"(a2), "r"(a3), "r"(b0), "r"(b1));
}

// ---------------- fused weight prep ----------------
#define PS_W1  10752
#define PSI2   (2 * 4 * 64 * 144)
#define PSI3   (4 * 4 * 64 * 144)
#define PSI5   (8 * 3 * 64 * 272)
#define PS_WFC 139440
#define PTOT (PS_W1 + PSI2 + PSI3 + PSI5 + PS_WFC)

// one int8 byte of a weight image; layout [ct][tap][co64][CINP]
__device__ __forceinline__ void prep_wimg(const float* __restrict__ w, int8_t* img,
                                          int Cin, int K, int i) {
    const int CINP = Cin + 16;
    int j = i % CINP;
    int rest = i / CINP;
    int co_l = rest % 64;
    rest /= 64;
    int tap = rest % K;
    int ct = rest / K;
    int gco = ct * 64 + co_l;
    int8_t v = 0;
    if (j < Cin) {
        int wd = j >> 5, b = j & 31;
        int c = 128 * (wd >> 2) + 4 * b + (wd & 3);
        v = (w[((size_t)gco * Cin + c) * K + tap] >= 0.f) ? (int8_t)1 : (int8_t)-1;
    }
    img[(size_t)i] = v;   // i already linearizes [ct][tap][co][CINP]
}

__global__ void k_prep_all(const float* __restrict__ w1, const float* __restrict__ w2,
                           const float* __restrict__ w3, const float* __restrict__ w5,
                           const float* __restrict__ wfc) {
    int gid = blockIdx.x * blockDim.x + threadIdx.x;
    if (gid < PS_W1) {
        int co = gid / K1, k = gid % K1;
        g_w1t[k * C1 + co] = (w1[gid] >= 0.f) ? 0.1f : -0.1f;
        return;
    }
    gid -= PS_W1;
    if (gid < PSI2) { prep_wimg(w2, g_wi2, 128, 4, gid); return; }
    gid -= PSI2;
    if (gid < PSI3) { prep_wimg(w3, g_wi3, 128, 4, gid); return; }
    gid -= PSI3;
    if (gid < PSI5) { prep_wimg(w5, g_wi5, 256, 3, gid); return; }
    gid -= PSI5;
    if (gid < PS_WFC) {
        int i = gid;
        int word = i % 16;
        int rest = i / 16;
        int t = rest % P5;
        int m = rest / P5;
        uint32_t bits = 0;
        for (int b = 0; b < 32; b++) {
            int c = 128 * (word >> 2) + 4 * b + (word & 3);
            if (wfc[(size_t)m * (512 * P5) + (size_t)c * P5 + t] >= 0.f) bits |= (1u << b);
        }
        g_wfcp[((size_t)m * P5 + t) * 16 + word] = bits;
        return;
    }
}

// ---------------- conv1: fp32, stride 4, K=84, fused stats (proven R11) ----------------
__global__ __launch_bounds__(256) void k_conv1(const float* __restrict__ x,
                                               const float* __restrict__ b1) {
    __shared__ __align__(16) float ws2[K1 * C1];
    __shared__ __align__(16) float xs[212];
    int n = blockIdx.y;
    int tb = blockIdx.x * 32;
    int tid = threadIdx.x;

    for (int i = tid; i < K1 * C1; i += 256) ws2[i] = g_w1t[i];
    for (int i = tid; i < 212; i += 256) {
        int xi = tb * 4 + i;
        xs[i] = (xi < L1_IN) ? x[(size_t)n * L1_IN + xi] : 0.f;
    }
    __syncthreads();

    int cg = tid & 31, tg = tid >> 5;
    int c0 = cg * 4, t0 = tg * 4;
    const float4* xf4 = reinterpret_cast<const float4*>(xs);

    unsigned long long acc2[2][4] = {};
#pragma unroll
    for (int k4 = 0; k4 < 21; k4++) {
        float4 xv[4];
#pragma unroll
        for (int i = 0; i < 4; i++) xv[i] = xf4[t0 + i + k4];
#pragma unroll
        for (int j = 0; j < 4; j++) {
            int k = k4 * 4 + j;
            unsigned long long w0 = *reinterpret_cast<const unsigned long long*>(&ws2[k * C1 + c0]);
            unsigned long long w1 = *reinterpret_cast<const unsigned long long*>(&ws2[k * C1 + c0 + 2]);
#pragma unroll
            for (int i = 0; i < 4; i++) {
                unsigned long long xd = dup2(reinterpret_cast<const float*>(xv)[i * 4 + j]);
                acc2[0][i] = ffma2_(w0, xd, acc2[0][i]);
                acc2[1][i] = ffma2_(w1, xd, acc2[1][i]);
            }
        }
    }

    float v[4][4];
#pragma unroll
    for (int i = 0; i < 4; i++) {
        float lo, hi;
        unpack2(acc2[0][i], lo, hi); v[0][i] = lo; v[1][i] = hi;
        unpack2(acc2[1][i], lo, hi); v[2][i] = lo; v[3][i] = hi;
    }
    float4 bb = *reinterpret_cast<const float4*>(&b1[c0]);
    float bv[4] = {bb.x, bb.y, bb.z, bb.w};
    float ssum[4] = {0, 0, 0, 0}, ssq[4] = {0, 0, 0, 0};
#pragma unroll
    for (int i = 0; i < 4; i++) {
        int t = tb + t0 + i;
        if (t < L1) {
            float o0 = v[0][i] + bv[0], o1 = v[1][i] + bv[1];
            float o2 = v[2][i] + bv[2], o3 = v[3][i] + bv[3];
            *reinterpret_cast<float4*>(&g_h1[((size_t)n * L1 + t) * C1 + c0]) =
                make_float4(o0, o1, o2, o3);
            ssum[0] += o0; ssq[0] += o0 * o0;
            ssum[1] += o1; ssq[1] += o1 * o1;
            ssum[2] += o2; ssq[2] += o2 * o2;
            ssum[3] += o3; ssq[3] += o3 * o3;
        }
    }
    __syncthreads();
    float2* sred = reinterpret_cast<float2*>(ws2);
#pragma unroll
    for (int j = 0; j < 4; j++) sred[tg * 128 + c0 + j] = make_float2(ssum[j], ssq[j]);
    __syncthreads();
    if (tid < 128) {
        float s = 0.f, q = 0.f;
#pragma unroll
        for (int g = 0; g < 8; g++) { float2 vv = sred[g * 128 + tid]; s += vv.x; q += vv.y; }
        int part = blockIdx.x * 64 + n;
        g_fpart[(size_t)tid * 8000 + part] = make_float2(s, q);
    }
}

// ---------------- stat finalize ----------------
__global__ void k_stat2f(const float* __restrict__ gamma, const float* __restrict__ beta,
                         int NPART, double Rinv) {
    __shared__ double ss[256], sq[256];
    int c = blockIdx.x, tid = threadIdx.x;
    double s = 0.0, q = 0.0;
    for (int i = tid; i < NPART; i += 256) {
        float2 vv = g_fpart[(size_t)c * NPART + i];
        s += vv.x; q += vv.y;
    }
    ss[tid] = s; sq[tid] = q;
    __syncthreads();
    for (int o = 128; o > 0; o >>= 1) {
        if (tid < o) { ss[tid] += ss[tid + o]; sq[tid] += sq[tid + o]; }
        __syncthreads();
    }
    if (tid == 0) {
        double mu = ss[0] * Rinv;
        double var = sq[0] * Rinv - mu * mu;
        double inv = rsqrt(var + 1e-5);
        double A = inv * (double)gamma[c];
        g_A[c] = (float)A;
        g_B[c] = (float)((double)beta[c] - mu * A);
    }
}

__global__ void k_stat2i(const float* __restrict__ bias, const float* __restrict__ gamma,
                         const float* __restrict__ beta, int NPART, double Rinv) {
    __shared__ long long ss[256], sq[256];
    int c = blockIdx.x, tid = threadIdx.x;
    long long s = 0, q = 0;
    for (int i = tid; i < NPART; i += 256) {
        int2 vv = g_ipart[(size_t)c * NPART + i];
        s += vv.x; q += vv.y;
    }
    ss[tid] = s; sq[tid] = q;
    __syncthreads();
    for (int o = 128; o > 0; o >>= 1) {
        if (tid < o) { ss[tid] += ss[tid + o]; sq[tid] += sq[tid + o]; }
        __syncthreads();
    }
    if (tid == 0) {
        double mu_s = (double)ss[0] * Rinv;
        double Es2 = (double)sq[0] * Rinv;
        double var_h = 0.01 * (Es2 - mu_s * mu_s);
        double b = bias[c];
        double mu_h = 0.1 * mu_s + b;
        double inv = rsqrt(var_h + 1e-5);
        double g = gamma[c];
        double A = 0.1 * inv * g;
        double B = (b - mu_h) * inv * g + (double)beta[c];
        g_A[c] = (float)A;
        g_B[c] = (float)B;
    }
}

// ---------------- binarize + pool(2), vectorized nibble-ballot ----------------
__global__ void k_binpool_f2(const float* __restrict__ h, uint32_t* __restrict__ a) {
    int gw = blockIdx.x * 8 + (threadIdx.x >> 5);
    if (gw >= NB * P1) return;
    int lane = threadIdx.x & 31;
    int to = gw % P1, n = gw / P1;
    size_t base = ((size_t)n * L1 + (size_t)2 * to) * 128 + lane * 4;
    float4 v0 = *reinterpret_cast<const float4*>(h + base);
    float4 v1 = *reinterpret_cast<const float4*>(h + base + 128);
    float4 A = *reinterpret_cast<const float4*>(g_A + lane * 4);
    float4 B = *reinterpret_cast<const float4*>(g_B + lane * 4);
    unsigned m0 = __ballot_sync(0xFFFFFFFFu,
        (fmaf(v0.x, A.x, B.x) >= 0.f) | (fmaf(v1.x, A.x, B.x) >= 0.f));
    unsigned m1 = __ballot_sync(0xFFFFFFFFu,
        (fmaf(v0.y, A.y, B.y) >= 0.f) | (fmaf(v1.y, A.y, B.y) >= 0.f));
    unsigned m2 = __ballot_sync(0xFFFFFFFFu,
        (fmaf(v0.z, A.z, B.z) >= 0.f) | (fmaf(v1.z, A.z, B.z) >= 0.f));
    unsigned m3 = __ballot_sync(0xFFFFFFFFu,
        (fmaf(v0.w, A.w, B.w) >= 0.f) | (fmaf(v1.w, A.w, B.w) >= 0.f));
    if (lane == 0)
        *reinterpret_cast<uint4*>(a + (size_t)gw * 4) = make_uint4(m0, m1, m2, m3);
}

template <int C, int L, int LO>
__global__ void k_binpool_i2(const short* __restrict__ h, uint32_t* __restrict__ a) {
    constexpr int HW = C / 128;
    int gw = blockIdx.x * 8 + (threadIdx.x >> 5);
    if (gw >= NB * LO * HW) return;
    int lane = threadIdx.x & 31;
    int hwi = gw % HW;
    int r = gw / HW;
    int to = r % LO, n = r / LO;
    int c0 = hwi * 128 + lane * 4;
    size_t base = ((size_t)n * L + (size_t)2 * to) * C + c0;
    short4 s0 = *reinterpret_cast<const short4*>(h + base);
    short4 s1 = *reinterpret_cast<const short4*>(h + base + C);
    float4 A = *reinterpret_cast<const float4*>(g_A + c0);
    float4 B = *reinterpret_cast<const float4*>(g_B + c0);
    unsigned m0 = __ballot_sync(0xFFFFFFFFu,
        (fmaf((float)s0.x, A.x, B.x) >= 0.f) | (fmaf((float)s1.x, A.x, B.x) >= 0.f));
    unsigned m1 = __ballot_sync(0xFFFFFFFFu,
        (fmaf((float)s0.y, A.y, B.y) >= 0.f) | (fmaf((float)s1.y, A.y, B.y) >= 0.f));
    unsigned m2 = __ballot_sync(0xFFFFFFFFu,
        (fmaf((float)s0.z, A.z, B.z) >= 0.f) | (fmaf((float)s1.z, A.z, B.z) >= 0.f));
    unsigned m3 = __ballot_sync(0xFFFFFFFFu,
        (fmaf((float)s0.w, A.w, B.w) >= 0.f) | (fmaf((float)s1.w, A.w, B.w) >= 0.f));
    if (lane == 0)
        *reinterpret_cast<uint4*>(a + (size_t)r * (C / 32) + hwi * 4) =
            make_uint4(m0, m1, m2, m3);
}

// ---------------- binary conv via int8 mma.sync (IMMA), fused int stats ----------------
// Tile: 128 t x 64 co per block. A = activations int8 (expanded from bits, pad rows = 0),
// B = weight int8 images (global, pre-expanded). CINP = CIN+16 row padding -> conflict-free frags.
template <int CIN, int COUT, int K, int PAD>
__global__ __launch_bounds__(256, 1) void k_convi(const uint32_t* __restrict__ a,
                                                  const int8_t* __restrict__ wimg,
                                                  short* __restrict__ h,
                                                  int Lin, int Lout, int NPART) {
    constexpr int W = CIN / 32;
    constexpr int CINP = CIN + 16;
    constexpr int ROWS = 128 + K - 1;
    constexpr int CH = CIN / 32;
    constexpr int WB = K * 64 * CINP;
    extern __shared__ __align__(16) char dsm[];
    int8_t* Ws = reinterpret_cast<int8_t*>(dsm);
    int8_t* As = reinterpret_cast<int8_t*>(dsm + WB);
    __shared__ int2 sred[16 * 64];

    int tid = threadIdx.x;
    int n = blockIdx.z;
    int cob = blockIdx.y * 64;
    int tb = blockIdx.x * 128;

    // load weight image (plain copy)
    {
        const uint4* src = reinterpret_cast<const uint4*>(wimg + (size_t)blockIdx.y * WB);
        uint4* dst = reinterpret_cast<uint4*>(Ws);
        for (int i = tid; i < WB / 16; i += 256) dst[i] = src[i];
    }
    // expand activations bits -> +-1 int8 (pad rows -> 0); bit=1 -> +1 (0x01), bit=0 -> -1 (0xFF)
    for (int idx = tid; idx < ROWS * W; idx += 256) {
        int r = idx / W;
        int w = idx % W;
        int t = tb + r - PAD;
        bool valid = (t >= 0 && t < Lin);
        uint32_t bits = valid ? a[((size_t)n * Lin + t) * W + w] : 0u;
        uint32_t* dst = reinterpret_cast<uint32_t*>(As + r * CINP + w * 32);
#pragma unroll
        for (int p = 0; p < 8; p++) {
            uint32_t nib = (bits >> (4 * p)) & 15u;
            uint32_t mask = (nib * 0x00204081u) & 0x01010101u;
            dst[p] = valid ? (0xFFFFFFFFu ^ (mask * 0xFEu)) : 0u;
        }
    }
    __syncthreads();

    int wid = tid >> 5, lane = tid & 31;
    int g = lane >> 2, tig = lane & 3;
    int wc = wid >> 2, wt = wid & 3;           // 2 co-halves x 4 t-quarters

    int cfr[2][4][4] = {};                     // [mt][nt][reg]
#pragma unroll
    for (int k = 0; k < K; k++) {
#pragma unroll
        for (int ch = 0; ch < CH; ch++) {
            int kb = ch * 32 + tig * 4;
            uint32_t afr[2][4];
#pragma unroll
            for (int mt = 0; mt < 2; mt++) {
                const int8_t* ap = As + (wt * 32 + mt * 16 + k + g) * CINP + kb;
                afr[mt][0] = *reinterpret_cast<const uint32_t*>(ap);
                afr[mt][1] = *reinterpret_cast<const uint32_t*>(ap + 8 * CINP);
                afr[mt][2] = *reinterpret_cast<const uint32_t*>(ap + 16);
                afr[mt][3] = *reinterpret_cast<const uint32_t*>(ap + 8 * CINP + 16);
            }
#pragma unroll
            for (int nt = 0; nt < 4; nt++) {
                const int8_t* bp = Ws + (k * 64 + wc * 32 + nt * 8 + g) * CINP + kb;
                uint32_t b0 = *reinterpret_cast<const uint32_t*>(bp);
                uint32_t b1 = *reinterpret_cast<const uint32_t*>(bp + 16);
                imma16832(cfr[0][nt][0], cfr[0][nt][1], cfr[0][nt][2], cfr[0][nt][3],
                          afr[0][0], afr[0][1], afr[0][2], afr[0][3], b0, b1);
                imma16832(cfr[1][nt][0], cfr[1][nt][1], cfr[1][nt][2], cfr[1][nt][3],
                          afr[1][0], afr[1][1], afr[1][2], afr[1][3], b0, b1);
            }
        }
    }
    __syncthreads();                           // A region dead -> reuse as staging
    short* stage = reinterpret_cast<short*>(As);
#pragma unroll
    for (int mt = 0; mt < 2; mt++) {
#pragma unroll
        for (int nt = 0; nt < 4; nt++) {
            int tl = wt * 32 + mt * 16 + g;
            int cl = wc * 32 + nt * 8 + tig * 2;
            stage[tl * 64 + cl]           = (short)cfr[mt][nt][0];
            stage[tl * 64 + cl + 1]       = (short)cfr[mt][nt][1];
            stage[(tl + 8) * 64 + cl]     = (short)cfr[mt][nt][2];
            stage[(tl + 8) * 64 + cl + 1] = (short)cfr[mt][nt][3];
        }
    }
    __syncthreads();

    // epilogue: coalesced short4 stores + exact int stats
    int co0 = (tid & 15) * 4;
    int t0 = (tid >> 4) * 8;
    int ssum[4] = {}, ssq[4] = {};
#pragma unroll
    for (int i = 0; i < 8; i++) {
        int t = tb + t0 + i;
        short4 v = *reinterpret_cast<const short4*>(&stage[(t0 + i) * 64 + co0]);
        if (t < Lout) {
            *reinterpret_cast<short4*>(&h[((size_t)n * Lout + t) * COUT + cob + co0]) = v;
            ssum[0] += v.x; ssq[0] += (int)v.x * v.x;
            ssum[1] += v.y; ssq[1] += (int)v.y * v.y;
            ssum[2] += v.z; ssq[2] += (int)v.z * v.z;
            ssum[3] += v.w; ssq[3] += (int)v.w * v.w;
        }
    }
    int grp = tid >> 4;
#pragma unroll
    for (int j = 0; j < 4; j++) sred[grp * 64 + co0 + j] = make_int2(ssum[j], ssq[j]);
    __syncthreads();
    if (tid < 64) {
        int s = 0, q = 0;
#pragma unroll
        for (int gg = 0; gg < 16; gg++) { int2 vv = sred[gg * 64 + tid]; s += vv.x; q += vv.y; }
        int part = blockIdx.x * NB + n;
        g_ipart[(size_t)(cob + tid) * NPART + part] = make_int2(s, q);
    }
}

// ---------------- FC via popcount, a5 staged in smem ----------------
__global__ __launch_bounds__(256) void k_fc(float* __restrict__ out) {
    __shared__ uint32_t a5s[P5 * 16];
    int n = blockIdx.x;
    int tid = threadIdx.x;
    int wid = tid >> 5, lane = tid & 31;
    const uint32_t* av = &g_a5[(size_t)n * P5 * 16];
    for (int i = tid; i < P5 * 16; i += 256) a5s[i] = av[i];
    __syncthreads();
    for (int m = wid; m < NCLS; m += 8) {
        const uint32_t* wv = &g_wfcp[(size_t)m * P5 * 16];
        int p = 0;
        for (int i = lane; i < P5 * 16; i += 32) p += __popc(a5s[i] ^ wv[i]);
#pragma unroll
        for (int o = 16; o > 0; o >>= 1) p += __shfl_xor_sync(0xFFFFFFFFu, p, o);
        if (lane == 0) out[n * NCLS + m] = 0.1f * (float)(P5 * 512 - 2 * p);
    }
}

// ---------------- launch ----------------
extern "C" void kernel_launch(void* const* d_in, const int* in_sizes, int n_in,
                              void* d_out, int out_size) {
    const float* x   = (const float*)d_in[0];
    const float* w1  = (const float*)d_in[1];
    const float* b1  = (const float*)d_in[2];
    const float* g1  = (const float*)d_in[3];
    const float* be1 = (const float*)d_in[4];
    const float* w2  = (const float*)d_in[5];
    const float* b2  = (const float*)d_in[6];
    const float* g2  = (const float*)d_in[7];
    const float* be2 = (const float*)d_in[8];
    const float* w3  = (const float*)d_in[9];
    const float* b3  = (const float*)d_in[10];
    const float* g3  = (const float*)d_in[11];
    const float* be3 = (const float*)d_in[12];
    const float* w5  = (const float*)d_in[13];
    const float* b5  = (const float*)d_in[14];
    const float* g5  = (const float*)d_in[15];
    const float* be5 = (const float*)d_in[16];
    const float* wfc = (const float*)d_in[17];

    void *p_wi2, *p_wi3, *p_wi5;
    void *p_a1, *p_a2, *p_a3, *p_a5, *p_h2, *p_h3, *p_h5, *p_h1;
    cudaGetSymbolAddress(&p_wi2, g_wi2);
    cudaGetSymbolAddress(&p_wi3, g_wi3);
    cudaGetSymbolAddress(&p_wi5, g_wi5);
    cudaGetSymbolAddress(&p_a1, g_a1);
    cudaGetSymbolAddress(&p_a2, g_a2);
    cudaGetSymbolAddress(&p_a3, g_a3);
    cudaGetSymbolAddress(&p_a5, g_a5);
    cudaGetSymbolAddress(&p_h1, g_h1);
    cudaGetSymbolAddress(&p_h2, g_h2s);
    cudaGetSymbolAddress(&p_h3, g_h3s);
    cudaGetSymbolAddress(&p_h5, g_h5s);

    const int SM23 = 4 * 64 * 144 + 131 * 144;      // 55728
    const int SM5  = 3 * 64 * 272 + 130 * 272;      // 87584
    cudaFuncSetAttribute(k_convi<128, 128, 4, 2>, cudaFuncAttributeMaxDynamicSharedMemorySize, SM23);
    cudaFuncSetAttribute(k_convi<128, 256, 4, 1>, cudaFuncAttributeMaxDynamicSharedMemorySize, SM23);
    cudaFuncSetAttribute(k_convi<256, 512, 3, 2>, cudaFuncAttributeMaxDynamicSharedMemorySize, SM5);

    // fused weight prep
    k_prep_all<<<(PTOT + 255) / 256, 256>>>(w1, w2, w3, w5, wfc);

    // layer 1
    k_conv1<<<dim3(125, NB), 256>>>(x, b1);
    k_stat2f<<<C1, 256>>>(g1, be1, 8000, 1.0 / (double)(NB * L1));
    {
        int nw = NB * P1;
        k_binpool_f2<<<(nw + 7) / 8, 256>>>((const float*)p_h1, (uint32_t*)p_a1);
    }
    // layer 2 (IMMA)
    k_convi<128, 128, 4, 2><<<dim3(16, 2, NB), 256, SM23>>>(
        (const uint32_t*)p_a1, (const int8_t*)p_wi2, (short*)p_h2, P1, L2, 16 * NB);
    k_stat2i<<<128, 256>>>(b2, g2, be2, 16 * NB, 1.0 / (double)(NB * L2));
    {
        int nw = NB * P2;
        k_binpool_i2<128, L2, P2><<<(nw + 7) / 8, 256>>>((const short*)p_h2, (uint32_t*)p_a2);
    }
    // layer 3 (IMMA)
    k_convi<128, 256, 4, 1><<<dim3(8, 4, NB), 256, SM23>>>(
        (const uint32_t*)p_a2, (const int8_t*)p_wi3, (short*)p_h3, P2, L3, 8 * NB);
    k_stat2i<<<256, 256>>>(b3, g3, be3, 8 * NB, 1.0 / (double)(NB * L3));
    {
        int nw = NB * P3 * 2;
        k_binpool_i2<256, L3, P3><<<(nw + 7) / 8, 256>>>((const short*)p_h3, (uint32_t*)p_a3);
    }
    // layer 5 (IMMA)
    k_convi<256, 512, 3, 2><<<dim3(4, 8, NB), 256, SM5>>>(
        (const uint32_t*)p_a3, (const int8_t*)p_wi5, (short*)p_h5, P3, L5, 4 * NB);
    k_stat2i<<<512, 256>>>(b5, g5, be5, 4 * NB, 1.0 / (double)(NB * L5));
    {
        int nw = NB * P5 * 4;
        k_binpool_i2<512, L5, P5><<<(nw + 7) / 8, 256>>>((const short*)p_h5, (uint32_t*)p_a5);
    }
    // fc
    k_fc<<<NB, 256>>>((float*)d_out);
}